// round 13
// baseline (speedup 1.0000x reference)
#include <cuda_runtime.h>
#include <cuda_bf16.h>
#include <cuda_fp16.h>
#include <cstdint>

#define NN 10000
#define NE 160000
#define DM 256
#define NH 8
#define HD 32
#define SCALE 0.17677669529663687f  // 1/sqrt(32)

// ---------------- device scratch (no dynamic allocation allowed) ------------
__device__ float g_Q[NN * DM];
__device__ __half g_Kh[NN * DM];   // fp16 K for the edge pass
__device__ __half g_Vh[NN * DM];   // fp16 V for the edge pass

// bf16 two-term split operands for tensor-core GEMMs
__device__ __nv_bfloat16 g_Ahi[NN * DM];
__device__ __nv_bfloat16 g_Alo[NN * DM];
// W matrices transposed: g_B*[z][n][k] = W_z[k][n], z in {q,k,v,o}
__device__ __nv_bfloat16 g_Bhi[4 * DM * DM];
__device__ __nv_bfloat16 g_Blo[4 * DM * DM];

// CSR over src. g_cnt zeroed at module load; re-zeroed at END of each run.
__device__ int g_cnt[NN];
__device__ int g_off[NN + 1];
__device__ int g_cur[NN];
__device__ int g_edst[NE];

__device__ __forceinline__ uint32_t smem_u32(const void* p) {
    uint32_t a;
    asm("{ .reg .u64 t; cvta.to.shared.u64 t, %1; cvt.u32.u64 %0, t; }"
        : "=r"(a) : "l"(p));
    return a;
}

__device__ __forceinline__ void cp_async16(uint32_t saddr, const void* gaddr,
                                           uint32_t src_sz) {
    asm volatile("cp.async.cg.shared.global [%0], [%1], 16, %2;"
                 :: "r"(saddr), "l"(gaddr), "r"(src_sz));
}
__device__ __forceinline__ void cp_commit() {
    asm volatile("cp.async.commit_group;" ::: "memory");
}
template <int N>
__device__ __forceinline__ void cp_wait() {
    asm volatile("cp.async.wait_group %0;" :: "n"(N) : "memory");
}

// ---------------------------------------------------------------------------
// CSR build: histogram (cnt pre-zeroed), scan, scatter, end-rezero
// ---------------------------------------------------------------------------
__global__ void hist_kernel(const int* __restrict__ src) {
    int e = blockIdx.x * blockDim.x + threadIdx.x;
    if (e < NE) atomicAdd(&g_cnt[src[e]], 1);
}

__global__ void scan_kernel() {
    __shared__ int wsum[32];
    int t = threadIdx.x;
    int lane = t & 31;
    int warp = t >> 5;
    int base = t * 10;

    int local[10];
    int s = 0;
#pragma unroll
    for (int j = 0; j < 10; j++) {
        int idx = base + j;
        int c = (idx < NN) ? g_cnt[idx] : 0;
        local[j] = s;
        s += c;
    }
    int inc = s;
#pragma unroll
    for (int o = 1; o < 32; o <<= 1) {
        int v = __shfl_up_sync(0xFFFFFFFFu, inc, o);
        if (lane >= o) inc += v;
    }
    if (lane == 31) wsum[warp] = inc;
    __syncthreads();
    if (warp == 0) {
        int w = wsum[lane];
        int wi = w;
#pragma unroll
        for (int o = 1; o < 32; o <<= 1) {
            int v = __shfl_up_sync(0xFFFFFFFFu, wi, o);
            if (lane >= o) wi += v;
        }
        wsum[lane] = wi - w;
    }
    __syncthreads();
    int texcl = wsum[warp] + (inc - s);
#pragma unroll
    for (int j = 0; j < 10; j++) {
        int idx = base + j;
        if (idx < NN) {
            int o = texcl + local[j];
            g_off[idx] = o;
            g_cur[idx] = o;
        }
    }
    if (t == 1023) g_off[NN] = texcl + s;
}

__global__ void scatter_kernel(const int* __restrict__ src,
                               const int* __restrict__ dst) {
    int e = blockIdx.x * blockDim.x + threadIdx.x;
    if (e >= NE) return;
    int pos = atomicAdd(&g_cur[src[e]], 1);
    g_edst[pos] = dst[e];
}

__global__ void rezero_kernel() {
    int i = blockIdx.x * blockDim.x + threadIdx.x;
    if (i < NN) g_cnt[i] = 0;
}

// ---------------------------------------------------------------------------
// Merged prep: x hi/lo split (float4-vectorized), W hi/lo transposed split
// ---------------------------------------------------------------------------
#define PREP_A4 (NN * DM / 4)                 // 640000 float4 items
#define PREP_TOTAL (PREP_A4 + 4 * DM * DM)    // + 262144 scalar W items

__global__ void prep_all_kernel(const float* __restrict__ x,
                                const float* __restrict__ Wq,
                                const float* __restrict__ Wk,
                                const float* __restrict__ Wv,
                                const float* __restrict__ Wo) {
    int i = blockIdx.x * blockDim.x + threadIdx.x;
    if (i < PREP_A4) {
        float4 v = ((const float4*)x)[i];
        __nv_bfloat16 h[4], l[4];
#pragma unroll
        for (int j = 0; j < 4; j++) {
            float f = (&v.x)[j];
            h[j] = __float2bfloat16(f);
            l[j] = __float2bfloat16(f - __bfloat162float(h[j]));
        }
        ((uint2*)g_Ahi)[i] = *(const uint2*)h;
        ((uint2*)g_Alo)[i] = *(const uint2*)l;
    } else if (i < PREP_TOTAL) {
        int j = i - PREP_A4;
        int z = j >> 16;
        int r = j & 0xFFFF;
        int k = r >> 8;
        int n = r & 255;
        const float* W = (z == 0) ? Wq : (z == 1) ? Wk : (z == 2) ? Wv : Wo;
        float w = W[k * DM + n];
        __nv_bfloat16 hi = __float2bfloat16(w);
        g_Bhi[z * DM * DM + n * DM + k] = hi;
        g_Blo[z * DM * DM + n * DM + k] = __float2bfloat16(w - __bfloat162float(hi));
    }
}

// ---------------------------------------------------------------------------
// Persistent QKV warp-MMA GEMM, cp.async double-buffered, BK=32, 2 CTAs/SM.
// 296 CTAs loop over 474 logical tiles (79 m x 2 n x 3 z) -> one wave,
// no quantization tail. Block tile 128x128, 8 warps (2m x 4n), 8 k-chunks.
// 3 passes (hh, lh, hl) from registers. Epilogue: z==0 -> fp32 Q;
// z==1/2 -> fp16 K/V.
// ---------------------------------------------------------------------------
#define SSTR 40
#define SM_CHUNK (128 * SSTR)
#define STAGE_ELEMS (4 * SM_CHUNK)
#define GEMM_SMEM (2 * STAGE_ELEMS * 2)  // 81920 B
#define MT ((NN + 127) / 128)            // 79 m-tiles
#define NTILES (MT * 2 * 3)              // 474
#define GEMM_GRID 296                    // 148 SMs x 2 CTAs

#define LDSM_X4(r0, r1, r2, r3, addr) \
    asm volatile("ldmatrix.sync.aligned.m8n8.x4.shared.b16 {%0,%1,%2,%3}, [%4];" \
                 : "=r"(r0), "=r"(r1), "=r"(r2), "=r"(r3) : "r"(addr))
#define LDSM_X2(r0, r1, addr) \
    asm volatile("ldmatrix.sync.aligned.m8n8.x2.shared.b16 {%0,%1}, [%2];" \
                 : "=r"(r0), "=r"(r1) : "r"(addr))
#define MMA_BF16(acc, a, b0, b1) \
    asm volatile("mma.sync.aligned.m16n8k16.row.col.f32.bf16.bf16.f32 " \
                 "{%0,%1,%2,%3}, {%4,%5,%6,%7}, {%8,%9}, {%0,%1,%2,%3};" \
                 : "+f"((acc)[0]), "+f"((acc)[1]), "+f"((acc)[2]), "+f"((acc)[3]) \
                 : "r"((a)[0]), "r"((a)[1]), "r"((a)[2]), "r"((a)[3]), \
                   "r"(b0), "r"(b1))

__global__ void __launch_bounds__(256, 2)
mma_gemm_kernel(const __nv_bfloat16* __restrict__ Ahi,
                const __nv_bfloat16* __restrict__ Alo, int M) {
    extern __shared__ __nv_bfloat16 sm[];

    const int tid = threadIdx.x;
    const int wid = tid >> 5;
    const int lane = tid & 31;
    const int wm = wid & 1;
    const int wn = wid >> 1;

    const int l_r = tid >> 2;
    const int l_c8 = (tid & 3) << 3;

    const int a_r = lane & 15;
    const int a_c = (lane >> 4) << 3;
    const int b_r = lane & 7;
    const int b_c = ((lane >> 3) & 1) << 3;

#pragma unroll 1
    for (int t = blockIdx.x; t < NTILES; t += GEMM_GRID) {
        const int m_i = t % MT;
        const int rest = t / MT;
        const int n_i = rest & 1;
        const int z = rest >> 1;
        const int m0 = m_i * 128;
        const int n0 = n_i * 128;
        const __nv_bfloat16* Bhi = g_Bhi + (size_t)z * DM * DM;
        const __nv_bfloat16* Blo = g_Blo + (size_t)z * DM * DM;

        auto preload = [&](int kc, int s) {
            __nv_bfloat16* base = sm + s * STAGE_ELEMS;
            uint32_t sAhi = smem_u32(base);
            uint32_t sAlo = smem_u32(base + SM_CHUNK);
            uint32_t sBhi = smem_u32(base + 2 * SM_CHUNK);
            uint32_t sBlo = smem_u32(base + 3 * SM_CHUNK);
            const int k0 = kc * 32;
#pragma unroll
            for (int it = 0; it < 2; it++) {
                int r = it * 64 + l_r;
                int gm = m0 + r;
                uint32_t soff = (uint32_t)(r * SSTR + l_c8) * 2;
                uint32_t szA = (gm < M) ? 16u : 0u;
                size_t ga = (size_t)gm * DM + k0 + l_c8;
                cp_async16(sAhi + soff, Ahi + ga, szA);
                cp_async16(sAlo + soff, Alo + ga, szA);
                size_t gb = (size_t)(n0 + r) * DM + k0 + l_c8;
                cp_async16(sBhi + soff, Bhi + gb, 16u);
                cp_async16(sBlo + soff, Blo + gb, 16u);
            }
            cp_commit();
        };

        float acc[4][4][4];
#pragma unroll
        for (int i = 0; i < 4; i++)
#pragma unroll
            for (int j = 0; j < 4; j++)
#pragma unroll
                for (int r = 0; r < 4; r++) acc[i][j][r] = 0.f;

        preload(0, 0);

#pragma unroll 1
        for (int kc = 0; kc < 8; kc++) {
            if (kc < 7) {
                preload(kc + 1, (kc + 1) & 1);
                cp_wait<1>();
            } else {
                cp_wait<0>();
            }
            __syncthreads();

            __nv_bfloat16* base = sm + (kc & 1) * STAGE_ELEMS;
            __nv_bfloat16* sAhi = base;
            __nv_bfloat16* sAlo = base + SM_CHUNK;
            __nv_bfloat16* sBhi = base + 2 * SM_CHUNK;
            __nv_bfloat16* sBlo = base + 3 * SM_CHUNK;

#pragma unroll
            for (int ks = 0; ks < 2; ks++) {
                const int koff = ks * 16;
                uint32_t ah[4][4], al[4][4];
#pragma unroll
                for (int i = 0; i < 4; i++) {
                    int row = wm * 64 + i * 16 + a_r;
                    LDSM_X4(ah[i][0], ah[i][1], ah[i][2], ah[i][3],
                            smem_u32(&sAhi[row * SSTR + koff + a_c]));
                    LDSM_X4(al[i][0], al[i][1], al[i][2], al[i][3],
                            smem_u32(&sAlo[row * SSTR + koff + a_c]));
                }
                uint32_t b[4][2];
#pragma unroll
                for (int j = 0; j < 4; j++) {
                    int row = wn * 32 + j * 8 + b_r;
                    LDSM_X2(b[j][0], b[j][1],
                            smem_u32(&sBhi[row * SSTR + koff + b_c]));
                }
#pragma unroll
                for (int i = 0; i < 4; i++)
#pragma unroll
                    for (int j = 0; j < 4; j++) MMA_BF16(acc[i][j], ah[i], b[j][0], b[j][1]);
#pragma unroll
                for (int i = 0; i < 4; i++)
#pragma unroll
                    for (int j = 0; j < 4; j++) MMA_BF16(acc[i][j], al[i], b[j][0], b[j][1]);
#pragma unroll
                for (int j = 0; j < 4; j++) {
                    int row = wn * 32 + j * 8 + b_r;
                    LDSM_X2(b[j][0], b[j][1],
                            smem_u32(&sBlo[row * SSTR + koff + b_c]));
                }
#pragma unroll
                for (int i = 0; i < 4; i++)
#pragma unroll
                    for (int j = 0; j < 4; j++) MMA_BF16(acc[i][j], ah[i], b[j][0], b[j][1]);
            }
            __syncthreads();
        }

        const int er = lane >> 2;
        const int ec = (lane & 3) << 1;
        if (z == 0) {
#pragma unroll
            for (int i = 0; i < 4; i++) {
                int gm0 = m0 + wm * 64 + i * 16 + er;
#pragma unroll
                for (int j = 0; j < 4; j++) {
                    int gc = n0 + wn * 32 + j * 8 + ec;
                    if (gm0 < M)
                        *(float2*)(g_Q + (size_t)gm0 * DM + gc) =
                            make_float2(acc[i][j][0], acc[i][j][1]);
                    if (gm0 + 8 < M)
                        *(float2*)(g_Q + (size_t)(gm0 + 8) * DM + gc) =
                            make_float2(acc[i][j][2], acc[i][j][3]);
                }
            }
        } else {
            __half* H = (z == 1) ? g_Kh : g_Vh;
#pragma unroll
            for (int i = 0; i < 4; i++) {
                int gm0 = m0 + wm * 64 + i * 16 + er;
#pragma unroll
                for (int j = 0; j < 4; j++) {
                    int gc = n0 + wn * 32 + j * 8 + ec;
                    if (gm0 < M)
                        *(__half2*)(H + (size_t)gm0 * DM + gc) =
                            __floats2half2_rn(acc[i][j][0], acc[i][j][1]);
                    if (gm0 + 8 < M)
                        *(__half2*)(H + (size_t)(gm0 + 8) * DM + gc) =
                            __floats2half2_rn(acc[i][j][2], acc[i][j][3]);
                }
            }
        }
    }
}

// ---------------------------------------------------------------------------
// Output GEMM + residual + LayerNorm fused.
// Block tile 64x256, 8 warps each owning a 32-col stripe; accs parked in
// smem then warp-per-row LN writes d_out.
// ---------------------------------------------------------------------------
#define FA_CHUNK (64 * SSTR)
#define FB_CHUNK (256 * SSTR)
#define FSTAGE (2 * FA_CHUNK + 2 * FB_CHUNK)  // 25600 elems
#define FUSED_SMEM (2 * FSTAGE * 2)           // 102400 B

__global__ void __launch_bounds__(256, 2)
gemm_ln_kernel(const __nv_bfloat16* __restrict__ Ahi,
               const __nv_bfloat16* __restrict__ Alo,
               const float* __restrict__ x,
               const float* __restrict__ gamma,
               const float* __restrict__ beta,
               float* __restrict__ out, int M) {
    extern __shared__ __nv_bfloat16 sm[];

    const int tid = threadIdx.x;
    const int wid = tid >> 5;
    const int lane = tid & 31;
    const int wn = wid;
    const __nv_bfloat16* Bhi = g_Bhi + (size_t)3 * DM * DM;
    const __nv_bfloat16* Blo = g_Blo + (size_t)3 * DM * DM;
    const int m0 = blockIdx.x * 64;

    const int l_r = tid >> 2;
    const int l_c8 = (tid & 3) << 3;

    auto preload = [&](int kc, int s) {
        __nv_bfloat16* base = sm + s * FSTAGE;
        uint32_t sAhi = smem_u32(base);
        uint32_t sAlo = smem_u32(base + FA_CHUNK);
        uint32_t sBhi = smem_u32(base + 2 * FA_CHUNK);
        uint32_t sBlo = smem_u32(base + 2 * FA_CHUNK + FB_CHUNK);
        const int k0 = kc * 32;
        {
            int r = l_r;
            int gm = m0 + r;
            uint32_t soff = (uint32_t)(r * SSTR + l_c8) * 2;
            uint32_t szA = (gm < M) ? 16u : 0u;
            size_t ga = (size_t)gm * DM + k0 + l_c8;
            cp_async16(sAhi + soff, Ahi + ga, szA);
            cp_async16(sAlo + soff, Alo + ga, szA);
        }
#pragma unroll
        for (int it = 0; it < 4; it++) {
            int r = it * 64 + l_r;
            uint32_t soff = (uint32_t)(r * SSTR + l_c8) * 2;
            size_t gb = (size_t)r * DM + k0 + l_c8;
            cp_async16(sBhi + soff, Bhi + gb, 16u);
            cp_async16(sBlo + soff, Blo + gb, 16u);
        }
        cp_commit();
    };

    float acc[4][4][4];
#pragma unroll
    for (int i = 0; i < 4; i++)
#pragma unroll
        for (int j = 0; j < 4; j++)
#pragma unroll
            for (int r = 0; r < 4; r++) acc[i][j][r] = 0.f;

    const int a_r = lane & 15;
    const int a_c = (lane >> 4) << 3;
    const int b_r = lane & 7;
    const int b_c = ((lane >> 3) & 1) << 3;

    preload(0, 0);

#pragma unroll 1
    for (int kc = 0; kc < 8; kc++) {
        if (kc < 7) {
            preload(kc + 1, (kc + 1) & 1);
            cp_wait<1>();
        } else {
            cp_wait<0>();
        }
        __syncthreads();

        __nv_bfloat16* base = sm + (kc & 1) * FSTAGE;
        __nv_bfloat16* sAhi = base;
        __nv_bfloat16* sAlo = base + FA_CHUNK;
        __nv_bfloat16* sBhi = base + 2 * FA_CHUNK;
        __nv_bfloat16* sBlo = base + 2 * FA_CHUNK + FB_CHUNK;

#pragma unroll
        for (int ks = 0; ks < 2; ks++) {
            const int koff = ks * 16;
            uint32_t ah[4][4], al[4][4];
#pragma unroll
            for (int i = 0; i < 4; i++) {
                int row = i * 16 + a_r;
                LDSM_X4(ah[i][0], ah[i][1], ah[i][2], ah[i][3],
                        smem_u32(&sAhi[row * SSTR + koff + a_c]));
                LDSM_X4(al[i][0], al[i][1], al[i][2], al[i][3],
                        smem_u32(&sAlo[row * SSTR + koff + a_c]));
            }
            uint32_t b[4][2];
#pragma unroll
            for (int j = 0; j < 4; j++) {
                int row = wn * 32 + j * 8 + b_r;
                LDSM_X2(b[j][0], b[j][1],
                        smem_u32(&sBhi[row * SSTR + koff + b_c]));
            }
#pragma unroll
            for (int i = 0; i < 4; i++)
#pragma unroll
                for (int j = 0; j < 4; j++) MMA_BF16(acc[i][j], ah[i], b[j][0], b[j][1]);
#pragma unroll
            for (int i = 0; i < 4; i++)
#pragma unroll
                for (int j = 0; j < 4; j++) MMA_BF16(acc[i][j], al[i], b[j][0], b[j][1]);
#pragma unroll
            for (int j = 0; j < 4; j++) {
                int row = wn * 32 + j * 8 + b_r;
                LDSM_X2(b[j][0], b[j][1],
                        smem_u32(&sBlo[row * SSTR + koff + b_c]));
            }
#pragma unroll
            for (int i = 0; i < 4; i++)
#pragma unroll
                for (int j = 0; j < 4; j++) MMA_BF16(acc[i][j], ah[i], b[j][0], b[j][1]);
        }
        __syncthreads();
    }

    // ---- park tile in smem: sOut[64][256] ----
    float* sOut = (float*)sm;
    const int er = lane >> 2;
    const int ec = (lane & 3) << 1;
#pragma unroll
    for (int i = 0; i < 4; i++) {
        int r0 = i * 16 + er;
#pragma unroll
        for (int j = 0; j < 4; j++) {
            int c = wn * 32 + j * 8 + ec;
            sOut[r0 * 256 + c] = acc[i][j][0];
            sOut[r0 * 256 + c + 1] = acc[i][j][1];
            sOut[(r0 + 8) * 256 + c] = acc[i][j][2];
            sOut[(r0 + 8) * 256 + c + 1] = acc[i][j][3];
        }
    }
    __syncthreads();

    // ---- residual + LN: warp per row ----
    const float4* g4 = (const float4*)gamma;
    const float4* b4 = (const float4*)beta;
    float4 ga = g4[2 * lane], gb = g4[2 * lane + 1];
    float4 ba = b4[2 * lane], bb = b4[2 * lane + 1];

#pragma unroll 1
    for (int rr = 0; rr < 8; rr++) {
        int r = wid * 8 + rr;
        int gm = m0 + r;
        if (gm >= M) break;
        const float4* x4 = (const float4*)(x + (size_t)gm * DM);
        float4 xa = x4[2 * lane], xb = x4[2 * lane + 1];
        const float* srow = sOut + r * 256 + 8 * lane;
        float v[8];
#pragma unroll
        for (int j = 0; j < 4; j++) v[j] = srow[j] + (&xa.x)[j];
#pragma unroll
        for (int j = 0; j < 4; j++) v[4 + j] = srow[4 + j] + (&xb.x)[j];

        float s = 0.f;
#pragma unroll
        for (int j = 0; j < 8; j++) s += v[j];
#pragma unroll
        for (int o = 16; o; o >>= 1) s += __shfl_xor_sync(0xFFFFFFFFu, s, o);
        float mu = s * (1.f / DM);

        float sq = 0.f;
#pragma unroll
        for (int j = 0; j < 8; j++) {
            float dv = v[j] - mu;
            sq += dv * dv;
        }
#pragma unroll
        for (int o = 16; o; o >>= 1) sq += __shfl_xor_sync(0xFFFFFFFFu, sq, o);
        float rstd = rsqrtf(sq * (1.f / DM) + 1e-5f);

        float4 r0, r1;
        r0.x = (v[0] - mu) * rstd * ga.x + ba.x;
        r0.y = (v[1] - mu) * rstd * ga.y + ba.y;
        r0.z = (v[2] - mu) * rstd * ga.z + ba.z;
        r0.w = (v[3] - mu) * rstd * ga.w + ba.w;
        r1.x = (v[4] - mu) * rstd * gb.x + bb.x;
        r1.y = (v[5] - mu) * rstd * gb.y + bb.y;
        r1.z = (v[6] - mu) * rstd * gb.z + bb.z;
        r1.w = (v[7] - mu) * rstd * gb.w + bb.w;

        float4* out4 = (float4*)(out + (size_t)gm * DM);
        out4[2 * lane] = r0;
        out4[2 * lane + 1] = r1;
    }
}

// ---------------------------------------------------------------------------
// Node aggregation: warp per node. Q (fp32) in regs; neighbor K/V rows read
// as fp16. Softmax in fp32 registers; writes hi/lo bf16 split directly.
// ---------------------------------------------------------------------------
__global__ void node_agg_kernel() {
    int n = blockIdx.x * (blockDim.x >> 5) + (threadIdx.x >> 5);
    if (n >= NN) return;
    int lane = threadIdx.x & 31;

    const float4* q4 = (const float4*)(g_Q + (size_t)n * DM);
    float4 qa = q4[2 * lane], qb = q4[2 * lane + 1];
    float q[8] = {qa.x, qa.y, qa.z, qa.w, qb.x, qb.y, qb.z, qb.w};

    int beg = g_off[n];
    int end = g_off[n + 1];

    float acc[8] = {0.f, 0.f, 0.f, 0.f, 0.f, 0.f, 0.f, 0.f};
    float den = 0.f;

    int d = (beg < end) ? __ldg(&g_edst[beg]) : 0;
#pragma unroll 1
    for (int i = beg; i < end; i++) {
        int dn = (i + 1 < end) ? __ldg(&g_edst[i + 1]) : 0;
        uint4 kr = *(const uint4*)(g_Kh + (size_t)d * DM + 8 * lane);
        uint4 vr = *(const uint4*)(g_Vh + (size_t)d * DM + 8 * lane);

        const __half2* kh = (const __half2*)&kr;
        float2 k0 = __half22float2(kh[0]);
        float2 k1 = __half22float2(kh[1]);
        float2 k2 = __half22float2(kh[2]);
        float2 k3 = __half22float2(kh[3]);

        float p = q[0] * k0.x + q[1] * k0.y + q[2] * k1.x + q[3] * k1.y +
                  q[4] * k2.x + q[5] * k2.y + q[6] * k3.x + q[7] * k3.y;
        p += __shfl_xor_sync(0xFFFFFFFFu, p, 1);
        p += __shfl_xor_sync(0xFFFFFFFFu, p, 2);

        float ex = __expf(p * SCALE);
        den += ex;

        const __half2* vh = (const __half2*)&vr;
        float2 v0 = __half22float2(vh[0]);
        float2 v1 = __half22float2(vh[1]);
        float2 v2 = __half22float2(vh[2]);
        float2 v3 = __half22float2(vh[3]);
        acc[0] += ex * v0.x; acc[1] += ex * v0.y;
        acc[2] += ex * v1.x; acc[3] += ex * v1.y;
        acc[4] += ex * v2.x; acc[5] += ex * v2.y;
        acc[6] += ex * v3.x; acc[7] += ex * v3.y;
        d = dn;
    }

    float inv = (den > 0.f) ? 1.f / den : 0.f;
    __nv_bfloat16 hi8[8], lo8[8];
#pragma unroll
    for (int j = 0; j < 8; j++) {
        float v = acc[j] * inv;
        __nv_bfloat16 hi = __float2bfloat16(v);
        hi8[j] = hi;
        lo8[j] = __float2bfloat16(v - __bfloat162float(hi));
    }
    size_t base = (size_t)n * DM + 8 * lane;
    *(uint4*)(g_Ahi + base) = *(const uint4*)hi8;
    *(uint4*)(g_Alo + base) = *(const uint4*)lo8;
}

// ---------------------------------------------------------------------------
extern "C" void kernel_launch(void* const* d_in, const int* in_sizes, int n_in,
                              void* d_out, int out_size) {
    const float* x     = (const float*)d_in[0];
    const int*   eidx  = (const int*)d_in[1];
    const float* Wq    = (const float*)d_in[2];
    const float* Wk    = (const float*)d_in[3];
    const float* Wv    = (const float*)d_in[4];
    const float* Wo    = (const float*)d_in[5];
    const float* gamma = (const float*)d_in[6];
    const float* beta  = (const float*)d_in[7];
    float* out = (float*)d_out;

    const int* src = eidx;
    const int* dst = eidx + NE;

    __nv_bfloat16* Ahip = nullptr; cudaGetSymbolAddress((void**)&Ahip, g_Ahi);
    __nv_bfloat16* Alop = nullptr; cudaGetSymbolAddress((void**)&Alop, g_Alo);

    cudaFuncSetAttribute(mma_gemm_kernel,
                         cudaFuncAttributeMaxDynamicSharedMemorySize, GEMM_SMEM);
    cudaFuncSetAttribute(gemm_ln_kernel,
                         cudaFuncAttributeMaxDynamicSharedMemorySize, FUSED_SMEM);

    // side stream + fork/join events (handles created once; no device mem)
    static cudaStream_t s2 = nullptr;
    static cudaEvent_t eA = nullptr, eB = nullptr, eE = nullptr;
    if (s2 == nullptr) {
        cudaStreamCreateWithFlags(&s2, cudaStreamNonBlocking);
        cudaEventCreateWithFlags(&eA, cudaEventDisableTiming);
        cudaEventCreateWithFlags(&eB, cudaEventDisableTiming);
        cudaEventCreateWithFlags(&eE, cudaEventDisableTiming);
    }

    // fork at graph root: CSR build depends only on edge_index
    cudaEventRecord(eA, 0);
    cudaStreamWaitEvent(s2, eA, 0);
    hist_kernel<<<(NE + 255) / 256, 256, 0, s2>>>(src);
    scan_kernel<<<1, 1024, 0, s2>>>();
    scatter_kernel<<<(NE + 255) / 256, 256, 0, s2>>>(src, dst);
    cudaEventRecord(eB, s2);
    rezero_kernel<<<(NN + 255) / 256, 256, 0, s2>>>();  // for next execution
    cudaEventRecord(eE, s2);

    // main stream: prep -> persistent QKV GEMM (concurrent with CSR build)
    prep_all_kernel<<<(PREP_TOTAL + 255) / 256, 256>>>(x, Wq, Wk, Wv, Wo);
    mma_gemm_kernel<<<GEMM_GRID, 256, GEMM_SMEM>>>(Ahip, Alop, NN);

    // join: aggregation needs QKV (main) and CSR (side)
    cudaStreamWaitEvent(0, eB, 0);
    node_agg_kernel<<<(NN + 7) / 8, 256>>>();

    // fused output GEMM + residual + LayerNorm -> d_out
    gemm_ln_kernel<<<(NN + 63) / 64, 256, FUSED_SMEM>>>(Ahip, Alop, x, gamma,
                                                        beta, out, NN);

    // join rezero into the graph before capture ends
    cudaStreamWaitEvent(0, eE, 0);
}

// round 14
// speedup vs baseline: 1.0961x; 1.0961x over previous
#include <cuda_runtime.h>
#include <cuda_bf16.h>
#include <cuda_fp16.h>
#include <cstdint>

#define NN 10000
#define NE 160000
#define DM 256
#define NH 8
#define HD 32
#define SCALE 0.17677669529663687f  // 1/sqrt(32)

// ---------------- device scratch (no dynamic allocation allowed) ------------
__device__ float g_Q[NN * DM];
__device__ __half g_Kh[NN * DM];   // fp16 K for the edge pass
__device__ __half g_Vh[NN * DM];   // fp16 V for the edge pass
__device__ __half g_Af16[NN * DM]; // f16 aggregated attn (A of output GEMM)

// bf16 two-term split operands for the QKV GEMM
__device__ __nv_bfloat16 g_Ahi[NN * DM];
__device__ __nv_bfloat16 g_Alo[NN * DM];
// W q/k/v transposed bf16 hi/lo: g_B*[z][n][k] = W_z[k][n], z in {q,k,v}
__device__ __nv_bfloat16 g_Bhi[3 * DM * DM];
__device__ __nv_bfloat16 g_Blo[3 * DM * DM];
// Wo transposed f16 hi/lo (for the f16 output GEMM)
__device__ __half g_WOhi[DM * DM];
__device__ __half g_WOlo[DM * DM];

// CSR over src. g_cnt zeroed at module load; re-zeroed at END of each run.
__device__ int g_cnt[NN];
__device__ int g_off[NN + 1];
__device__ int g_cur[NN];
__device__ int g_edst[NE];

__device__ __forceinline__ uint32_t smem_u32(const void* p) {
    uint32_t a;
    asm("{ .reg .u64 t; cvta.to.shared.u64 t, %1; cvt.u32.u64 %0, t; }"
        : "=r"(a) : "l"(p));
    return a;
}

__device__ __forceinline__ void cp_async16(uint32_t saddr, const void* gaddr,
                                           uint32_t src_sz) {
    asm volatile("cp.async.cg.shared.global [%0], [%1], 16, %2;"
                 :: "r"(saddr), "l"(gaddr), "r"(src_sz));
}
__device__ __forceinline__ void cp_commit() {
    asm volatile("cp.async.commit_group;" ::: "memory");
}
template <int N>
__device__ __forceinline__ void cp_wait() {
    asm volatile("cp.async.wait_group %0;" :: "n"(N) : "memory");
}

// ---------------------------------------------------------------------------
// CSR build: histogram (cnt pre-zeroed), scan, scatter, end-rezero
// ---------------------------------------------------------------------------
__global__ void hist_kernel(const int* __restrict__ src) {
    int e = blockIdx.x * blockDim.x + threadIdx.x;
    if (e < NE) atomicAdd(&g_cnt[src[e]], 1);
}

__global__ void scan_kernel() {
    __shared__ int wsum[32];
    int t = threadIdx.x;
    int lane = t & 31;
    int warp = t >> 5;
    int base = t * 10;

    int local[10];
    int s = 0;
#pragma unroll
    for (int j = 0; j < 10; j++) {
        int idx = base + j;
        int c = (idx < NN) ? g_cnt[idx] : 0;
        local[j] = s;
        s += c;
    }
    int inc = s;
#pragma unroll
    for (int o = 1; o < 32; o <<= 1) {
        int v = __shfl_up_sync(0xFFFFFFFFu, inc, o);
        if (lane >= o) inc += v;
    }
    if (lane == 31) wsum[warp] = inc;
    __syncthreads();
    if (warp == 0) {
        int w = wsum[lane];
        int wi = w;
#pragma unroll
        for (int o = 1; o < 32; o <<= 1) {
            int v = __shfl_up_sync(0xFFFFFFFFu, wi, o);
            if (lane >= o) wi += v;
        }
        wsum[lane] = wi - w;
    }
    __syncthreads();
    int texcl = wsum[warp] + (inc - s);
#pragma unroll
    for (int j = 0; j < 10; j++) {
        int idx = base + j;
        if (idx < NN) {
            int o = texcl + local[j];
            g_off[idx] = o;
            g_cur[idx] = o;
        }
    }
    if (t == 1023) g_off[NN] = texcl + s;
}

__global__ void scatter_kernel(const int* __restrict__ src,
                               const int* __restrict__ dst) {
    int e = blockIdx.x * blockDim.x + threadIdx.x;
    if (e >= NE) return;
    int pos = atomicAdd(&g_cur[src[e]], 1);
    g_edst[pos] = dst[e];
}

__global__ void rezero_kernel() {
    int i = blockIdx.x * blockDim.x + threadIdx.x;
    if (i < NN) g_cnt[i] = 0;
}

// ---------------------------------------------------------------------------
// Merged prep: x hi/lo bf16 (float4-vectorized), W q/k/v bf16 hi/lo
// transposed, Wo f16 hi/lo transposed.
// ---------------------------------------------------------------------------
#define PREP_A4 (NN * DM / 4)                 // 640000 float4 items
#define PREP_TOTAL (PREP_A4 + 4 * DM * DM)    // + 4x 65536 scalar W items

__global__ void prep_all_kernel(const float* __restrict__ x,
                                const float* __restrict__ Wq,
                                const float* __restrict__ Wk,
                                const float* __restrict__ Wv,
                                const float* __restrict__ Wo) {
    int i = blockIdx.x * blockDim.x + threadIdx.x;
    if (i < PREP_A4) {
        float4 v = ((const float4*)x)[i];
        __nv_bfloat16 h[4], l[4];
#pragma unroll
        for (int j = 0; j < 4; j++) {
            float f = (&v.x)[j];
            h[j] = __float2bfloat16(f);
            l[j] = __float2bfloat16(f - __bfloat162float(h[j]));
        }
        ((uint2*)g_Ahi)[i] = *(const uint2*)h;
        ((uint2*)g_Alo)[i] = *(const uint2*)l;
    } else if (i < PREP_TOTAL) {
        int j = i - PREP_A4;
        int z = j >> 16;
        int r = j & 0xFFFF;
        int k = r >> 8;
        int n = r & 255;
        if (z < 3) {
            const float* W = (z == 0) ? Wq : (z == 1) ? Wk : Wv;
            float w = W[k * DM + n];
            __nv_bfloat16 hi = __float2bfloat16(w);
            g_Bhi[z * DM * DM + n * DM + k] = hi;
            g_Blo[z * DM * DM + n * DM + k] =
                __float2bfloat16(w - __bfloat162float(hi));
        } else {
            float w = Wo[k * DM + n];
            __half hi = __float2half_rn(w);
            g_WOhi[n * DM + k] = hi;
            g_WOlo[n * DM + k] = __float2half_rn(w - __half2float(hi));
        }
    }
}

// ---------------------------------------------------------------------------
// QKV warp-MMA GEMM, cp.async double-buffered, BK=32 (2 CTAs/SM):
// block 128x128, 8 warps (2m x 4n), warp tile 64x32, 8 k-chunks.
// 3 passes (hh, lh, hl) from registers. Epilogue: z==0 -> fp32 Q;
// z==1/2 -> fp16 K/V.
// ---------------------------------------------------------------------------
#define SSTR 40
#define SM_CHUNK (128 * SSTR)
#define STAGE_ELEMS (4 * SM_CHUNK)
#define GEMM_SMEM (2 * STAGE_ELEMS * 2)  // 81920 B

#define LDSM_X4(r0, r1, r2, r3, addr) \
    asm volatile("ldmatrix.sync.aligned.m8n8.x4.shared.b16 {%0,%1,%2,%3}, [%4];" \
                 : "=r"(r0), "=r"(r1), "=r"(r2), "=r"(r3) : "r"(addr))
#define LDSM_X2(r0, r1, addr) \
    asm volatile("ldmatrix.sync.aligned.m8n8.x2.shared.b16 {%0,%1}, [%2];" \
                 : "=r"(r0), "=r"(r1) : "r"(addr))
#define MMA_BF16(acc, a, b0, b1) \
    asm volatile("mma.sync.aligned.m16n8k16.row.col.f32.bf16.bf16.f32 " \
                 "{%0,%1,%2,%3}, {%4,%5,%6,%7}, {%8,%9}, {%0,%1,%2,%3};" \
                 : "+f"((acc)[0]), "+f"((acc)[1]), "+f"((acc)[2]), "+f"((acc)[3]) \
                 : "r"((a)[0]), "r"((a)[1]), "r"((a)[2]), "r"((a)[3]), \
                   "r"(b0), "r"(b1))
#define MMA_F16(acc, a, b0, b1) \
    asm volatile("mma.sync.aligned.m16n8k16.row.col.f32.f16.f16.f32 " \
                 "{%0,%1,%2,%3}, {%4,%5,%6,%7}, {%8,%9}, {%0,%1,%2,%3};" \
                 : "+f"((acc)[0]), "+f"((acc)[1]), "+f"((acc)[2]), "+f"((acc)[3]) \
                 : "r"((a)[0]), "r"((a)[1]), "r"((a)[2]), "r"((a)[3]), \
                   "r"(b0), "r"(b1))

__global__ void __launch_bounds__(256, 2)
mma_gemm_kernel(const __nv_bfloat16* __restrict__ Ahi,
                const __nv_bfloat16* __restrict__ Alo, int M) {
    extern __shared__ __nv_bfloat16 sm[];

    const int tid = threadIdx.x;
    const int wid = tid >> 5;
    const int lane = tid & 31;
    const int wm = wid & 1;
    const int wn = wid >> 1;
    const int z = blockIdx.z;
    const __nv_bfloat16* Bhi = g_Bhi + (size_t)z * DM * DM;
    const __nv_bfloat16* Blo = g_Blo + (size_t)z * DM * DM;
    const int m0 = blockIdx.x * 128;
    const int n0 = blockIdx.y * 128;

    const int l_r = tid >> 2;
    const int l_c8 = (tid & 3) << 3;

    auto preload = [&](int kc, int s) {
        __nv_bfloat16* base = sm + s * STAGE_ELEMS;
        uint32_t sAhi = smem_u32(base);
        uint32_t sAlo = smem_u32(base + SM_CHUNK);
        uint32_t sBhi = smem_u32(base + 2 * SM_CHUNK);
        uint32_t sBlo = smem_u32(base + 3 * SM_CHUNK);
        const int k0 = kc * 32;
#pragma unroll
        for (int it = 0; it < 2; it++) {
            int r = it * 64 + l_r;
            int gm = m0 + r;
            uint32_t soff = (uint32_t)(r * SSTR + l_c8) * 2;
            uint32_t szA = (gm < M) ? 16u : 0u;
            size_t ga = (size_t)gm * DM + k0 + l_c8;
            cp_async16(sAhi + soff, Ahi + ga, szA);
            cp_async16(sAlo + soff, Alo + ga, szA);
            size_t gb = (size_t)(n0 + r) * DM + k0 + l_c8;
            cp_async16(sBhi + soff, Bhi + gb, 16u);
            cp_async16(sBlo + soff, Blo + gb, 16u);
        }
        cp_commit();
    };

    float acc[4][4][4];
#pragma unroll
    for (int i = 0; i < 4; i++)
#pragma unroll
        for (int j = 0; j < 4; j++)
#pragma unroll
            for (int r = 0; r < 4; r++) acc[i][j][r] = 0.f;

    const int a_r = lane & 15;
    const int a_c = (lane >> 4) << 3;
    const int b_r = lane & 7;
    const int b_c = ((lane >> 3) & 1) << 3;

    preload(0, 0);

#pragma unroll 1
    for (int kc = 0; kc < 8; kc++) {
        if (kc < 7) {
            preload(kc + 1, (kc + 1) & 1);
            cp_wait<1>();
        } else {
            cp_wait<0>();
        }
        __syncthreads();

        __nv_bfloat16* base = sm + (kc & 1) * STAGE_ELEMS;
        __nv_bfloat16* sAhi = base;
        __nv_bfloat16* sAlo = base + SM_CHUNK;
        __nv_bfloat16* sBhi = base + 2 * SM_CHUNK;
        __nv_bfloat16* sBlo = base + 3 * SM_CHUNK;

#pragma unroll
        for (int ks = 0; ks < 2; ks++) {
            const int koff = ks * 16;
            uint32_t ah[4][4], al[4][4];
#pragma unroll
            for (int i = 0; i < 4; i++) {
                int row = wm * 64 + i * 16 + a_r;
                LDSM_X4(ah[i][0], ah[i][1], ah[i][2], ah[i][3],
                        smem_u32(&sAhi[row * SSTR + koff + a_c]));
                LDSM_X4(al[i][0], al[i][1], al[i][2], al[i][3],
                        smem_u32(&sAlo[row * SSTR + koff + a_c]));
            }
            uint32_t b[4][2];
#pragma unroll
            for (int j = 0; j < 4; j++) {
                int row = wn * 32 + j * 8 + b_r;
                LDSM_X2(b[j][0], b[j][1],
                        smem_u32(&sBhi[row * SSTR + koff + b_c]));
            }
#pragma unroll
            for (int i = 0; i < 4; i++)
#pragma unroll
                for (int j = 0; j < 4; j++) MMA_BF16(acc[i][j], ah[i], b[j][0], b[j][1]);
#pragma unroll
            for (int i = 0; i < 4; i++)
#pragma unroll
                for (int j = 0; j < 4; j++) MMA_BF16(acc[i][j], al[i], b[j][0], b[j][1]);
#pragma unroll
            for (int j = 0; j < 4; j++) {
                int row = wn * 32 + j * 8 + b_r;
                LDSM_X2(b[j][0], b[j][1],
                        smem_u32(&sBlo[row * SSTR + koff + b_c]));
            }
#pragma unroll
            for (int i = 0; i < 4; i++)
#pragma unroll
                for (int j = 0; j < 4; j++) MMA_BF16(acc[i][j], ah[i], b[j][0], b[j][1]);
        }
        __syncthreads();
    }

    const int er = lane >> 2;
    const int ec = (lane & 3) << 1;
    if (z == 0) {
#pragma unroll
        for (int i = 0; i < 4; i++) {
            int gm0 = m0 + wm * 64 + i * 16 + er;
#pragma unroll
            for (int j = 0; j < 4; j++) {
                int gc = n0 + wn * 32 + j * 8 + ec;
                if (gm0 < M)
                    *(float2*)(g_Q + (size_t)gm0 * DM + gc) =
                        make_float2(acc[i][j][0], acc[i][j][1]);
                if (gm0 + 8 < M)
                    *(float2*)(g_Q + (size_t)(gm0 + 8) * DM + gc) =
                        make_float2(acc[i][j][2], acc[i][j][3]);
            }
        }
    } else {
        __half* H = (z == 1) ? g_Kh : g_Vh;
#pragma unroll
        for (int i = 0; i < 4; i++) {
            int gm0 = m0 + wm * 64 + i * 16 + er;
#pragma unroll
            for (int j = 0; j < 4; j++) {
                int gc = n0 + wn * 32 + j * 8 + ec;
                if (gm0 < M)
                    *(__half2*)(H + (size_t)gm0 * DM + gc) =
                        __floats2half2_rn(acc[i][j][0], acc[i][j][1]);
                if (gm0 + 8 < M)
                    *(__half2*)(H + (size_t)(gm0 + 8) * DM + gc) =
                        __floats2half2_rn(acc[i][j][2], acc[i][j][3]);
            }
        }
    }
}

// ---------------------------------------------------------------------------
// Output GEMM (f16 operands, fp32 accum) + residual + LayerNorm fused.
// A = f16(agg) single operand; B = f16 Wo hi + lo, 2 passes.
// Block tile 64x256, 8 warps each owning a 32-col stripe; accs parked in
// smem then warp-per-row LN writes d_out.
// ---------------------------------------------------------------------------
#define FA_CHUNK (64 * SSTR)
#define FB_CHUNK (256 * SSTR)
#define FSTAGE (FA_CHUNK + 2 * FB_CHUNK)  // 23040 half elems
#define FUSED_SMEM (2 * FSTAGE * 2)       // 92160 B (>= 65536 for sOut)

__global__ void __launch_bounds__(256, 2)
gemm_ln_kernel(const float* __restrict__ x,
               const float* __restrict__ gamma,
               const float* __restrict__ beta,
               float* __restrict__ out, int M) {
    extern __shared__ __half smh[];

    const int tid = threadIdx.x;
    const int wid = tid >> 5;
    const int lane = tid & 31;
    const int wn = wid;
    const int m0 = blockIdx.x * 64;

    const int l_r = tid >> 2;
    const int l_c8 = (tid & 3) << 3;

    auto preload = [&](int kc, int s) {
        __half* base = smh + s * FSTAGE;
        uint32_t sA = smem_u32(base);
        uint32_t sBhi = smem_u32(base + FA_CHUNK);
        uint32_t sBlo = smem_u32(base + FA_CHUNK + FB_CHUNK);
        const int k0 = kc * 32;
        {
            int r = l_r;
            int gm = m0 + r;
            uint32_t soff = (uint32_t)(r * SSTR + l_c8) * 2;
            uint32_t szA = (gm < M) ? 16u : 0u;
            cp_async16(sA + soff, g_Af16 + (size_t)gm * DM + k0 + l_c8, szA);
        }
#pragma unroll
        for (int it = 0; it < 4; it++) {
            int r = it * 64 + l_r;
            uint32_t soff = (uint32_t)(r * SSTR + l_c8) * 2;
            size_t gb = (size_t)r * DM + k0 + l_c8;
            cp_async16(sBhi + soff, g_WOhi + gb, 16u);
            cp_async16(sBlo + soff, g_WOlo + gb, 16u);
        }
        cp_commit();
    };

    float acc[4][4][4];
#pragma unroll
    for (int i = 0; i < 4; i++)
#pragma unroll
        for (int j = 0; j < 4; j++)
#pragma unroll
            for (int r = 0; r < 4; r++) acc[i][j][r] = 0.f;

    const int a_r = lane & 15;
    const int a_c = (lane >> 4) << 3;
    const int b_r = lane & 7;
    const int b_c = ((lane >> 3) & 1) << 3;

    preload(0, 0);

#pragma unroll 1
    for (int kc = 0; kc < 8; kc++) {
        if (kc < 7) {
            preload(kc + 1, (kc + 1) & 1);
            cp_wait<1>();
        } else {
            cp_wait<0>();
        }
        __syncthreads();

        __half* base = smh + (kc & 1) * FSTAGE;
        __half* sA = base;
        __half* sBhi = base + FA_CHUNK;
        __half* sBlo = base + FA_CHUNK + FB_CHUNK;

#pragma unroll
        for (int ks = 0; ks < 2; ks++) {
            const int koff = ks * 16;
            uint32_t a[4][4];
#pragma unroll
            for (int i = 0; i < 4; i++) {
                int row = i * 16 + a_r;
                LDSM_X4(a[i][0], a[i][1], a[i][2], a[i][3],
                        smem_u32(&sA[row * SSTR + koff + a_c]));
            }
            uint32_t b[4][2];
#pragma unroll
            for (int j = 0; j < 4; j++) {
                int row = wn * 32 + j * 8 + b_r;
                LDSM_X2(b[j][0], b[j][1],
                        smem_u32(&sBhi[row * SSTR + koff + b_c]));
            }
#pragma unroll
            for (int i = 0; i < 4; i++)
#pragma unroll
                for (int j = 0; j < 4; j++) MMA_F16(acc[i][j], a[i], b[j][0], b[j][1]);
#pragma unroll
            for (int j = 0; j < 4; j++) {
                int row = wn * 32 + j * 8 + b_r;
                LDSM_X2(b[j][0], b[j][1],
                        smem_u32(&sBlo[row * SSTR + koff + b_c]));
            }
#pragma unroll
            for (int i = 0; i < 4; i++)
#pragma unroll
                for (int j = 0; j < 4; j++) MMA_F16(acc[i][j], a[i], b[j][0], b[j][1]);
        }
        __syncthreads();
    }

    // ---- park tile in smem: sOut[64][256] ----
    float* sOut = (float*)smh;
    const int er = lane >> 2;
    const int ec = (lane & 3) << 1;
#pragma unroll
    for (int i = 0; i < 4; i++) {
        int r0 = i * 16 + er;
#pragma unroll
        for (int j = 0; j < 4; j++) {
            int c = wn * 32 + j * 8 + ec;
            sOut[r0 * 256 + c] = acc[i][j][0];
            sOut[r0 * 256 + c + 1] = acc[i][j][1];
            sOut[(r0 + 8) * 256 + c] = acc[i][j][2];
            sOut[(r0 + 8) * 256 + c + 1] = acc[i][j][3];
        }
    }
    __syncthreads();

    // ---- residual + LN: warp per row ----
    const float4* g4 = (const float4*)gamma;
    const float4* b4 = (const float4*)beta;
    float4 ga = g4[2 * lane], gb = g4[2 * lane + 1];
    float4 ba = b4[2 * lane], bb = b4[2 * lane + 1];

#pragma unroll 1
    for (int rr = 0; rr < 8; rr++) {
        int r = wid * 8 + rr;
        int gm = m0 + r;
        if (gm >= M) break;
        const float4* x4 = (const float4*)(x + (size_t)gm * DM);
        float4 xa = x4[2 * lane], xb = x4[2 * lane + 1];
        const float* srow = sOut + r * 256 + 8 * lane;
        float v[8];
#pragma unroll
        for (int j = 0; j < 4; j++) v[j] = srow[j] + (&xa.x)[j];
#pragma unroll
        for (int j = 0; j < 4; j++) v[4 + j] = srow[4 + j] + (&xb.x)[j];

        float s = 0.f;
#pragma unroll
        for (int j = 0; j < 8; j++) s += v[j];
#pragma unroll
        for (int o = 16; o; o >>= 1) s += __shfl_xor_sync(0xFFFFFFFFu, s, o);
        float mu = s * (1.f / DM);

        float sq = 0.f;
#pragma unroll
        for (int j = 0; j < 8; j++) {
            float dv = v[j] - mu;
            sq += dv * dv;
        }
#pragma unroll
        for (int o = 16; o; o >>= 1) sq += __shfl_xor_sync(0xFFFFFFFFu, sq, o);
        float rstd = rsqrtf(sq * (1.f / DM) + 1e-5f);

        float4 r0, r1;
        r0.x = (v[0] - mu) * rstd * ga.x + ba.x;
        r0.y = (v[1] - mu) * rstd * ga.y + ba.y;
        r0.z = (v[2] - mu) * rstd * ga.z + ba.z;
        r0.w = (v[3] - mu) * rstd * ga.w + ba.w;
        r1.x = (v[4] - mu) * rstd * gb.x + bb.x;
        r1.y = (v[5] - mu) * rstd * gb.y + bb.y;
        r1.z = (v[6] - mu) * rstd * gb.z + bb.z;
        r1.w = (v[7] - mu) * rstd * gb.w + bb.w;

        float4* out4 = (float4*)(out + (size_t)gm * DM);
        out4[2 * lane] = r0;
        out4[2 * lane + 1] = r1;
    }
}

// ---------------------------------------------------------------------------
// Node aggregation: warp per node. Q (fp32) in regs; neighbor K/V rows read
// as fp16. Softmax in fp32 registers; writes f16 A operand directly.
// ---------------------------------------------------------------------------
__global__ void node_agg_kernel() {
    int n = blockIdx.x * (blockDim.x >> 5) + (threadIdx.x >> 5);
    if (n >= NN) return;
    int lane = threadIdx.x & 31;

    const float4* q4 = (const float4*)(g_Q + (size_t)n * DM);
    float4 qa = q4[2 * lane], qb = q4[2 * lane + 1];
    float q[8] = {qa.x, qa.y, qa.z, qa.w, qb.x, qb.y, qb.z, qb.w};

    int beg = g_off[n];
    int end = g_off[n + 1];

    float acc[8] = {0.f, 0.f, 0.f, 0.f, 0.f, 0.f, 0.f, 0.f};
    float den = 0.f;

    int d = (beg < end) ? __ldg(&g_edst[beg]) : 0;
#pragma unroll 1
    for (int i = beg; i < end; i++) {
        int dn = (i + 1 < end) ? __ldg(&g_edst[i + 1]) : 0;
        uint4 kr = *(const uint4*)(g_Kh + (size_t)d * DM + 8 * lane);
        uint4 vr = *(const uint4*)(g_Vh + (size_t)d * DM + 8 * lane);

        const __half2* kh = (const __half2*)&kr;
        float2 k0 = __half22float2(kh[0]);
        float2 k1 = __half22float2(kh[1]);
        float2 k2 = __half22float2(kh[2]);
        float2 k3 = __half22float2(kh[3]);

        float p = q[0] * k0.x + q[1] * k0.y + q[2] * k1.x + q[3] * k1.y +
                  q[4] * k2.x + q[5] * k2.y + q[6] * k3.x + q[7] * k3.y;
        p += __shfl_xor_sync(0xFFFFFFFFu, p, 1);
        p += __shfl_xor_sync(0xFFFFFFFFu, p, 2);

        float ex = __expf(p * SCALE);
        den += ex;

        const __half2* vh = (const __half2*)&vr;
        float2 v0 = __half22float2(vh[0]);
        float2 v1 = __half22float2(vh[1]);
        float2 v2 = __half22float2(vh[2]);
        float2 v3 = __half22float2(vh[3]);
        acc[0] += ex * v0.x; acc[1] += ex * v0.y;
        acc[2] += ex * v1.x; acc[3] += ex * v1.y;
        acc[4] += ex * v2.x; acc[5] += ex * v2.y;
        acc[6] += ex * v3.x; acc[7] += ex * v3.y;
        d = dn;
    }

    float inv = (den > 0.f) ? 1.f / den : 0.f;
    __half h8[8];
#pragma unroll
    for (int j = 0; j < 8; j++) h8[j] = __float2half_rn(acc[j] * inv);
    *(uint4*)(g_Af16 + (size_t)n * DM + 8 * lane) = *(const uint4*)h8;
}

// ---------------------------------------------------------------------------
extern "C" void kernel_launch(void* const* d_in, const int* in_sizes, int n_in,
                              void* d_out, int out_size) {
    const float* x     = (const float*)d_in[0];
    const int*   eidx  = (const int*)d_in[1];
    const float* Wq    = (const float*)d_in[2];
    const float* Wk    = (const float*)d_in[3];
    const float* Wv    = (const float*)d_in[4];
    const float* Wo    = (const float*)d_in[5];
    const float* gamma = (const float*)d_in[6];
    const float* beta  = (const float*)d_in[7];
    float* out = (float*)d_out;

    const int* src = eidx;
    const int* dst = eidx + NE;

    __nv_bfloat16* Ahip = nullptr; cudaGetSymbolAddress((void**)&Ahip, g_Ahi);
    __nv_bfloat16* Alop = nullptr; cudaGetSymbolAddress((void**)&Alop, g_Alo);

    cudaFuncSetAttribute(mma_gemm_kernel,
                         cudaFuncAttributeMaxDynamicSharedMemorySize, GEMM_SMEM);
    cudaFuncSetAttribute(gemm_ln_kernel,
                         cudaFuncAttributeMaxDynamicSharedMemorySize, FUSED_SMEM);

    // side stream + fork/join events (handles created once; no device mem)
    static cudaStream_t s2 = nullptr;
    static cudaEvent_t eA = nullptr, eB = nullptr, eE = nullptr;
    if (s2 == nullptr) {
        cudaStreamCreateWithFlags(&s2, cudaStreamNonBlocking);
        cudaEventCreateWithFlags(&eA, cudaEventDisableTiming);
        cudaEventCreateWithFlags(&eB, cudaEventDisableTiming);
        cudaEventCreateWithFlags(&eE, cudaEventDisableTiming);
    }

    // fork at graph root: CSR build depends only on edge_index
    cudaEventRecord(eA, 0);
    cudaStreamWaitEvent(s2, eA, 0);
    hist_kernel<<<(NE + 255) / 256, 256, 0, s2>>>(src);
    scan_kernel<<<1, 1024, 0, s2>>>();
    scatter_kernel<<<(NE + 255) / 256, 256, 0, s2>>>(src, dst);
    cudaEventRecord(eB, s2);
    rezero_kernel<<<(NN + 255) / 256, 256, 0, s2>>>();  // for next execution
    cudaEventRecord(eE, s2);

    // main stream: prep -> QKV GEMMs (concurrent with CSR build)
    prep_all_kernel<<<(PREP_TOTAL + 255) / 256, 256>>>(x, Wq, Wk, Wv, Wo);
    dim3 gq((NN + 127) / 128, DM / 128, 3);
    mma_gemm_kernel<<<gq, 256, GEMM_SMEM>>>(Ahip, Alop, NN);

    // join: aggregation needs QKV (main) and CSR (side)
    cudaStreamWaitEvent(0, eB, 0);
    node_agg_kernel<<<(NN + 7) / 8, 256>>>();

    // fused f16 output GEMM + residual + LayerNorm -> d_out
    gemm_ln_kernel<<<(NN + 63) / 64, 256, FUSED_SMEM>>>(x, gamma, beta, out, NN);

    // join rezero into the graph before capture ends
    cudaStreamWaitEvent(0, eE, 0);
}

// round 16
// speedup vs baseline: 1.2228x; 1.1156x over previous
#include <cuda_runtime.h>
#include <cuda_bf16.h>
#include <cuda_fp16.h>
#include <cstdint>

#define NN 10000
#define NE 160000
#define DM 256
#define NH 8
#define HD 32
#define SCALE 0.17677669529663687f  // 1/sqrt(32)

// ---------------- device scratch (no dynamic allocation allowed) ------------
__device__ float g_Q[NN * DM];
__device__ __half g_Kh[NN * DM];   // fp16 K for the edge pass
__device__ __half g_Vh[NN * DM];   // fp16 V for the edge pass
__device__ __half g_Xf16[NN * DM]; // f16 node embeddings (A of QKV GEMM)
__device__ __half g_Af16[NN * DM]; // f16 aggregated attn (A of output GEMM)

// All 4 weight matrices, f16 hi/lo, transposed: g_W*[z][n][k] = W_z[k][n]
__device__ __half g_Whi[4 * DM * DM];
__device__ __half g_Wlo[4 * DM * DM];

// CSR over src. g_cnt zeroed at module load; re-zeroed at END of each run.
__device__ int g_cnt[NN];
__device__ int g_off[NN + 1];
__device__ int g_cur[NN];
__device__ int g_edst[NE];

__device__ __forceinline__ uint32_t smem_u32(const void* p) {
    uint32_t a;
    asm("{ .reg .u64 t; cvta.to.shared.u64 t, %1; cvt.u32.u64 %0, t; }"
        : "=r"(a) : "l"(p));
    return a;
}

__device__ __forceinline__ void cp_async16(uint32_t saddr, const void* gaddr,
                                           uint32_t src_sz) {
    asm volatile("cp.async.cg.shared.global [%0], [%1], 16, %2;"
                 :: "r"(saddr), "l"(gaddr), "r"(src_sz));
}
__device__ __forceinline__ void cp_commit() {
    asm volatile("cp.async.commit_group;" ::: "memory");
}
template <int N>
__device__ __forceinline__ void cp_wait() {
    asm volatile("cp.async.wait_group %0;" :: "n"(N) : "memory");
}

// ---------------------------------------------------------------------------
// CSR build: histogram (cnt pre-zeroed), scan, scatter, end-rezero
// ---------------------------------------------------------------------------
__global__ void hist_kernel(const int* __restrict__ src) {
    int e = blockIdx.x * blockDim.x + threadIdx.x;
    if (e < NE) atomicAdd(&g_cnt[src[e]], 1);
}

__global__ void scan_kernel() {
    __shared__ int wsum[32];
    int t = threadIdx.x;
    int lane = t & 31;
    int warp = t >> 5;
    int base = t * 10;

    int local[10];
    int s = 0;
#pragma unroll
    for (int j = 0; j < 10; j++) {
        int idx = base + j;
        int c = (idx < NN) ? g_cnt[idx] : 0;
        local[j] = s;
        s += c;
    }
    int inc = s;
#pragma unroll
    for (int o = 1; o < 32; o <<= 1) {
        int v = __shfl_up_sync(0xFFFFFFFFu, inc, o);
        if (lane >= o) inc += v;
    }
    if (lane == 31) wsum[warp] = inc;
    __syncthreads();
    if (warp == 0) {
        int w = wsum[lane];
        int wi = w;
#pragma unroll
        for (int o = 1; o < 32; o <<= 1) {
            int v = __shfl_up_sync(0xFFFFFFFFu, wi, o);
            if (lane >= o) wi += v;
        }
        wsum[lane] = wi - w;
    }
    __syncthreads();
    int texcl = wsum[warp] + (inc - s);
#pragma unroll
    for (int j = 0; j < 10; j++) {
        int idx = base + j;
        if (idx < NN) {
            int o = texcl + local[j];
            g_off[idx] = o;
            g_cur[idx] = o;
        }
    }
    if (t == 1023) g_off[NN] = texcl + s;
}

__global__ void scatter_kernel(const int* __restrict__ src,
                               const int* __restrict__ dst) {
    int e = blockIdx.x * blockDim.x + threadIdx.x;
    if (e >= NE) return;
    int pos = atomicAdd(&g_cur[src[e]], 1);
    g_edst[pos] = dst[e];
}

__global__ void rezero_kernel() {
    int i = blockIdx.x * blockDim.x + threadIdx.x;
    if (i < NN) g_cnt[i] = 0;
}

// ---------------------------------------------------------------------------
// Merged prep: x -> f16 (float4-vectorized), all W -> f16 hi/lo transposed
// ---------------------------------------------------------------------------
#define PREP_A4 (NN * DM / 4)                 // 640000 float4 items
#define PREP_TOTAL (PREP_A4 + 4 * DM * DM)    // + 4x 65536 scalar W items

__global__ void prep_all_kernel(const float* __restrict__ x,
                                const float* __restrict__ Wq,
                                const float* __restrict__ Wk,
                                const float* __restrict__ Wv,
                                const float* __restrict__ Wo) {
    int i = blockIdx.x * blockDim.x + threadIdx.x;
    if (i < PREP_A4) {
        float4 v = ((const float4*)x)[i];
        __half h[4];
#pragma unroll
        for (int j = 0; j < 4; j++) h[j] = __float2half_rn((&v.x)[j]);
        ((uint2*)g_Xf16)[i] = *(const uint2*)h;
    } else if (i < PREP_TOTAL) {
        int j = i - PREP_A4;
        int z = j >> 16;
        int r = j & 0xFFFF;
        int k = r >> 8;
        int n = r & 255;
        const float* W = (z == 0) ? Wq : (z == 1) ? Wk : (z == 2) ? Wv : Wo;
        float w = W[k * DM + n];
        __half hi = __float2half_rn(w);
        g_Whi[z * DM * DM + n * DM + k] = hi;
        g_Wlo[z * DM * DM + n * DM + k] = __float2half_rn(w - __half2float(hi));
    }
}

// ---------------------------------------------------------------------------
// QKV warp-MMA GEMM (f16 operands, fp32 accum), cp.async double-buffered,
// BK=32, 60KB smem -> 2 CTAs/SM. Block 128x128, 8 warps (2m x 4n).
// A = f16(x) single pass; B = f16 W hi + lo, 2 passes.
// Epilogue: z==0 -> fp32 Q; z==1/2 -> fp16 K/V.
// ---------------------------------------------------------------------------
#define SSTR 40
#define SM_CHUNK (128 * SSTR)
#define STAGE3 (3 * SM_CHUNK)            // A | Bhi | Blo
#define GEMM_SMEM (2 * STAGE3 * 2)       // 61440 B

#define LDSM_X4(r0, r1, r2, r3, addr) \
    asm volatile("ldmatrix.sync.aligned.m8n8.x4.shared.b16 {%0,%1,%2,%3}, [%4];" \
                 : "=r"(r0), "=r"(r1), "=r"(r2), "=r"(r3) : "r"(addr))
#define LDSM_X2(r0, r1, addr) \
    asm volatile("ldmatrix.sync.aligned.m8n8.x2.shared.b16 {%0,%1}, [%2];" \
                 : "=r"(r0), "=r"(r1) : "r"(addr))
#define MMA_F16(acc, a, b0, b1) \
    asm volatile("mma.sync.aligned.m16n8k16.row.col.f32.f16.f16.f32 " \
                 "{%0,%1,%2,%3}, {%4,%5,%6,%7}, {%8,%9}, {%0,%1,%2,%3};" \
                 : "+f"((acc)[0]), "+f"((acc)[1]), "+f"((acc)[2]), "+f"((acc)[3]) \
                 : "r"((a)[0]), "r"((a)[1]), "r"((a)[2]), "r"((a)[3]), \
                   "r"(b0), "r"(b1))

__global__ void __launch_bounds__(256, 2)
mma_gemm_kernel(int M) {
    extern __shared__ __half smh[];

    const int tid = threadIdx.x;
    const int wid = tid >> 5;
    const int lane = tid & 31;
    const int wm = wid & 1;
    const int wn = wid >> 1;
    const int z = blockIdx.z;
    const __half* Bhi = g_Whi + (size_t)z * DM * DM;
    const __half* Blo = g_Wlo + (size_t)z * DM * DM;
    const int m0 = blockIdx.x * 128;
    const int n0 = blockIdx.y * 128;

    const int l_r = tid >> 2;            // 0..63
    const int l_c8 = (tid & 3) << 3;     // 0,8,16,24

    auto preload = [&](int kc, int s) {
        __half* base = smh + s * STAGE3;
        uint32_t sA = smem_u32(base);
        uint32_t sBhi = smem_u32(base + SM_CHUNK);
        uint32_t sBlo = smem_u32(base + 2 * SM_CHUNK);
        const int k0 = kc * 32;
#pragma unroll
        for (int it = 0; it < 2; it++) {
            int r = it * 64 + l_r;
            int gm = m0 + r;
            uint32_t soff = (uint32_t)(r * SSTR + l_c8) * 2;
            uint32_t szA = (gm < M) ? 16u : 0u;
            cp_async16(sA + soff, g_Xf16 + (size_t)gm * DM + k0 + l_c8, szA);
            size_t gb = (size_t)(n0 + r) * DM + k0 + l_c8;
            cp_async16(sBhi + soff, Bhi + gb, 16u);
            cp_async16(sBlo + soff, Blo + gb, 16u);
        }
        cp_commit();
    };

    float acc[4][4][4];
#pragma unroll
    for (int i = 0; i < 4; i++)
#pragma unroll
        for (int j = 0; j < 4; j++)
#pragma unroll
            for (int r = 0; r < 4; r++) acc[i][j][r] = 0.f;

    const int a_r = lane & 15;
    const int a_c = (lane >> 4) << 3;
    const int b_r = lane & 7;
    const int b_c = ((lane >> 3) & 1) << 3;

    preload(0, 0);

#pragma unroll 1
    for (int kc = 0; kc < 8; kc++) {
        if (kc < 7) {
            preload(kc + 1, (kc + 1) & 1);
            cp_wait<1>();
        } else {
            cp_wait<0>();
        }
        __syncthreads();

        __half* base = smh + (kc & 1) * STAGE3;
        __half* sA = base;
        __half* sBhi = base + SM_CHUNK;
        __half* sBlo = base + 2 * SM_CHUNK;

#pragma unroll
        for (int ks = 0; ks < 2; ks++) {
            const int koff = ks * 16;
            uint32_t a[4][4];
#pragma unroll
            for (int i = 0; i < 4; i++) {
                int row = wm * 64 + i * 16 + a_r;
                LDSM_X4(a[i][0], a[i][1], a[i][2], a[i][3],
                        smem_u32(&sA[row * SSTR + koff + a_c]));
            }
            uint32_t b[4][2];
#pragma unroll
            for (int j = 0; j < 4; j++) {
                int row = wn * 32 + j * 8 + b_r;
                LDSM_X2(b[j][0], b[j][1],
                        smem_u32(&sBhi[row * SSTR + koff + b_c]));
            }
#pragma unroll
            for (int i = 0; i < 4; i++)
#pragma unroll
                for (int j = 0; j < 4; j++) MMA_F16(acc[i][j], a[i], b[j][0], b[j][1]);
#pragma unroll
            for (int j = 0; j < 4; j++) {
                int row = wn * 32 + j * 8 + b_r;
                LDSM_X2(b[j][0], b[j][1],
                        smem_u32(&sBlo[row * SSTR + koff + b_c]));
            }
#pragma unroll
            for (int i = 0; i < 4; i++)
#pragma unroll
                for (int j = 0; j < 4; j++) MMA_F16(acc[i][j], a[i], b[j][0], b[j][1]);
        }
        __syncthreads();
    }

    const int er = lane >> 2;
    const int ec = (lane & 3) << 1;
    if (z == 0) {
#pragma unroll
        for (int i = 0; i < 4; i++) {
            int gm0 = m0 + wm * 64 + i * 16 + er;
#pragma unroll
            for (int j = 0; j < 4; j++) {
                int gc = n0 + wn * 32 + j * 8 + ec;
                if (gm0 < M)
                    *(float2*)(g_Q + (size_t)gm0 * DM + gc) =
                        make_float2(acc[i][j][0], acc[i][j][1]);
                if (gm0 + 8 < M)
                    *(float2*)(g_Q + (size_t)(gm0 + 8) * DM + gc) =
                        make_float2(acc[i][j][2], acc[i][j][3]);
            }
        }
    } else {
        __half* H = (z == 1) ? g_Kh : g_Vh;
#pragma unroll
        for (int i = 0; i < 4; i++) {
            int gm0 = m0 + wm * 64 + i * 16 + er;
#pragma unroll
            for (int j = 0; j < 4; j++) {
                int gc = n0 + wn * 32 + j * 8 + ec;
                if (gm0 < M)
                    *(__half2*)(H + (size_t)gm0 * DM + gc) =
                        __floats2half2_rn(acc[i][j][0], acc[i][j][1]);
                if (gm0 + 8 < M)
                    *(__half2*)(H + (size_t)(gm0 + 8) * DM + gc) =
                        __floats2half2_rn(acc[i][j][2], acc[i][j][3]);
            }
        }
    }
}

// ---------------------------------------------------------------------------
// Output GEMM (f16 operands, fp32 accum) + residual + LayerNorm fused.
// A = f16(agg) single; B = f16 Wo hi + lo, 2 passes. Block tile 64x256,
// 8 warps each owning a 32-col stripe; accs parked in smem, warp-per-row LN.
// ---------------------------------------------------------------------------
#define FA_CHUNK (64 * SSTR)
#define FB_CHUNK (256 * SSTR)
#define FSTAGE (FA_CHUNK + 2 * FB_CHUNK)  // 23040 half elems
#define FUSED_SMEM (2 * FSTAGE * 2)       // 92160 B (>= 65536 for sOut)

__global__ void __launch_bounds__(256, 2)
gemm_ln_kernel(const float* __restrict__ x,
               const float* __restrict__ gamma,
               const float* __restrict__ beta,
               float* __restrict__ out, int M) {
    extern __shared__ __half smh[];

    const int tid = threadIdx.x;
    const int wid = tid >> 5;
    const int lane = tid & 31;
    const int wn = wid;
    const __half* Bhi = g_Whi + (size_t)3 * DM * DM;
    const __half* Blo = g_Wlo + (size_t)3 * DM * DM;
    const int m0 = blockIdx.x * 64;

    const int l_r = tid >> 2;
    const int l_c8 = (tid & 3) << 3;

    auto preload = [&](int kc, int s) {
        __half* base = smh + s * FSTAGE;
        uint32_t sA = smem_u32(base);
        uint32_t sBhi = smem_u32(base + FA_CHUNK);
        uint32_t sBlo = smem_u32(base + FA_CHUNK + FB_CHUNK);
        const int k0 = kc * 32;
        {
            int r = l_r;
            int gm = m0 + r;
            uint32_t soff = (uint32_t)(r * SSTR + l_c8) * 2;
            uint32_t szA = (gm < M) ? 16u : 0u;
            cp_async16(sA + soff, g_Af16 + (size_t)gm * DM + k0 + l_c8, szA);
        }
#pragma unroll
        for (int it = 0; it < 4; it++) {
            int r = it * 64 + l_r;
            uint32_t soff = (uint32_t)(r * SSTR + l_c8) * 2;
            size_t gb = (size_t)r * DM + k0 + l_c8;
            cp_async16(sBhi + soff, Bhi + gb, 16u);
            cp_async16(sBlo + soff, Blo + gb, 16u);
        }
        cp_commit();
    };

    float acc[4][4][4];
#pragma unroll
    for (int i = 0; i < 4; i++)
#pragma unroll
        for (int j = 0; j < 4; j++)
#pragma unroll
            for (int r = 0; r < 4; r++) acc[i][j][r] = 0.f;

    const int a_r = lane & 15;
    const int a_c = (lane >> 4) << 3;
    const int b_r = lane & 7;
    const int b_c = ((lane >> 3) & 1) << 3;

    preload(0, 0);

#pragma unroll 1
    for (int kc = 0; kc < 8; kc++) {
        if (kc < 7) {
            preload(kc + 1, (kc + 1) & 1);
            cp_wait<1>();
        } else {
            cp_wait<0>();
        }
        __syncthreads();

        __half* base = smh + (kc & 1) * FSTAGE;
        __half* sA = base;
        __half* sBhi = base + FA_CHUNK;
        __half* sBlo = base + FA_CHUNK + FB_CHUNK;

#pragma unroll
        for (int ks = 0; ks < 2; ks++) {
            const int koff = ks * 16;
            uint32_t a[4][4];
#pragma unroll
            for (int i = 0; i < 4; i++) {
                int row = i * 16 + a_r;
                LDSM_X4(a[i][0], a[i][1], a[i][2], a[i][3],
                        smem_u32(&sA[row * SSTR + koff + a_c]));
            }
            uint32_t b[4][2];
#pragma unroll
            for (int j = 0; j < 4; j++) {
                int row = wn * 32 + j * 8 + b_r;
                LDSM_X2(b[j][0], b[j][1],
                        smem_u32(&sBhi[row * SSTR + koff + b_c]));
            }
#pragma unroll
            for (int i = 0; i < 4; i++)
#pragma unroll
                for (int j = 0; j < 4; j++) MMA_F16(acc[i][j], a[i], b[j][0], b[j][1]);
#pragma unroll
            for (int j = 0; j < 4; j++) {
                int row = wn * 32 + j * 8 + b_r;
                LDSM_X2(b[j][0], b[j][1],
                        smem_u32(&sBlo[row * SSTR + koff + b_c]));
            }
#pragma unroll
            for (int i = 0; i < 4; i++)
#pragma unroll
                for (int j = 0; j < 4; j++) MMA_F16(acc[i][j], a[i], b[j][0], b[j][1]);
        }
        __syncthreads();
    }

    // ---- park tile in smem: sOut[64][256] ----
    float* sOut = (float*)smh;
    const int er = lane >> 2;
    const int ec = (lane & 3) << 1;
#pragma unroll
    for (int i = 0; i < 4; i++) {
        int r0 = i * 16 + er;
#pragma unroll
        for (int j = 0; j < 4; j++) {
            int c = wn * 32 + j * 8 + ec;
            sOut[r0 * 256 + c] = acc[i][j][0];
            sOut[r0 * 256 + c + 1] = acc[i][j][1];
            sOut[(r0 + 8) * 256 + c] = acc[i][j][2];
            sOut[(r0 + 8) * 256 + c + 1] = acc[i][j][3];
        }
    }
    __syncthreads();

    // ---- residual + LN: warp per row ----
    const float4* g4 = (const float4*)gamma;
    const float4* b4 = (const float4*)beta;
    float4 ga = g4[2 * lane], gb = g4[2 * lane + 1];
    float4 ba = b4[2 * lane], bb = b4[2 * lane + 1];

#pragma unroll 1
    for (int rr = 0; rr < 8; rr++) {
        int r = wid * 8 + rr;
        int gm = m0 + r;
        if (gm >= M) break;
        const float4* x4 = (const float4*)(x + (size_t)gm * DM);
        float4 xa = x4[2 * lane], xb = x4[2 * lane + 1];
        const float* srow = sOut + r * 256 + 8 * lane;
        float v[8];
#pragma unroll
        for (int j = 0; j < 4; j++) v[j] = srow[j] + (&xa.x)[j];
#pragma unroll
        for (int j = 0; j < 4; j++) v[4 + j] = srow[4 + j] + (&xb.x)[j];

        float s = 0.f;
#pragma unroll
        for (int j = 0; j < 8; j++) s += v[j];
#pragma unroll
        for (int o = 16; o; o >>= 1) s += __shfl_xor_sync(0xFFFFFFFFu, s, o);
        float mu = s * (1.f / DM);

        float sq = 0.f;
#pragma unroll
        for (int j = 0; j < 8; j++) {
            float dv = v[j] - mu;
            sq += dv * dv;
        }
#pragma unroll
        for (int o = 16; o; o >>= 1) sq += __shfl_xor_sync(0xFFFFFFFFu, sq, o);
        float rstd = rsqrtf(sq * (1.f / DM) + 1e-5f);

        float4 r0, r1;
        r0.x = (v[0] - mu) * rstd * ga.x + ba.x;
        r0.y = (v[1] - mu) * rstd * ga.y + ba.y;
        r0.z = (v[2] - mu) * rstd * ga.z + ba.z;
        r0.w = (v[3] - mu) * rstd * ga.w + ba.w;
        r1.x = (v[4] - mu) * rstd * gb.x + bb.x;
        r1.y = (v[5] - mu) * rstd * gb.y + bb.y;
        r1.z = (v[6] - mu) * rstd * gb.z + bb.z;
        r1.w = (v[7] - mu) * rstd * gb.w + bb.w;

        float4* out4 = (float4*)(out + (size_t)gm * DM);
        out4[2 * lane] = r0;
        out4[2 * lane + 1] = r1;
    }
}

// ---------------------------------------------------------------------------
// Node aggregation: warp per node. Q (fp32) in regs; neighbor K/V rows read
// as fp16. Softmax in fp32 registers; writes f16 A operand directly.
// ---------------------------------------------------------------------------
__global__ void node_agg_kernel() {
    int n = blockIdx.x * (blockDim.x >> 5) + (threadIdx.x >> 5);
    if (n >= NN) return;
    int lane = threadIdx.x & 31;

    const float4* q4 = (const float4*)(g_Q + (size_t)n * DM);
    float4 qa = q4[2 * lane], qb = q4[2 * lane + 1];
    float q[8] = {qa.x, qa.y, qa.z, qa.w, qb.x, qb.y, qb.z, qb.w};

    int beg = g_off[n];
    int end = g_off[n + 1];

    float acc[8] = {0.f, 0.f, 0.f, 0.f, 0.f, 0.f, 0.f, 0.f};
    float den = 0.f;

    int d = (beg < end) ? __ldg(&g_edst[beg]) : 0;
#pragma unroll 1
    for (int i = beg; i < end; i++) {
        int dn = (i + 1 < end) ? __ldg(&g_edst[i + 1]) : 0;
        uint4 kr = *(const uint4*)(g_Kh + (size_t)d * DM + 8 * lane);
        uint4 vr = *(const uint4*)(g_Vh + (size_t)d * DM + 8 * lane);

        const __half2* kh = (const __half2*)&kr;
        float2 k0 = __half22float2(kh[0]);
        float2 k1 = __half22float2(kh[1]);
        float2 k2 = __half22float2(kh[2]);
        float2 k3 = __half22float2(kh[3]);

        float p = q[0] * k0.x + q[1] * k0.y + q[2] * k1.x + q[3] * k1.y +
                  q[4] * k2.x + q[5] * k2.y + q[6] * k3.x + q[7] * k3.y;
        p += __shfl_xor_sync(0xFFFFFFFFu, p, 1);
        p += __shfl_xor_sync(0xFFFFFFFFu, p, 2);

        float ex = __expf(p * SCALE);
        den += ex;

        const __half2* vh = (const __half2*)&vr;
        float2 v0 = __half22float2(vh[0]);
        float2 v1 = __half22float2(vh[1]);
        float2 v2 = __half22float2(vh[2]);
        float2 v3 = __half22float2(vh[3]);
        acc[0] += ex * v0.x; acc[1] += ex * v0.y;
        acc[2] += ex * v1.x; acc[3] += ex * v1.y;
        acc[4] += ex * v2.x; acc[5] += ex * v2.y;
        acc[6] += ex * v3.x; acc[7] += ex * v3.y;
        d = dn;
    }

    float inv = (den > 0.f) ? 1.f / den : 0.f;
    __half h8[8];
#pragma unroll
    for (int j = 0; j < 8; j++) h8[j] = __float2half_rn(acc[j] * inv);
    *(uint4*)(g_Af16 + (size_t)n * DM + 8 * lane) = *(const uint4*)h8;
}

// ---------------------------------------------------------------------------
extern "C" void kernel_launch(void* const* d_in, const int* in_sizes, int n_in,
                              void* d_out, int out_size) {
    const float* x     = (const float*)d_in[0];
    const int*   eidx  = (const int*)d_in[1];
    const float* Wq    = (const float*)d_in[2];
    const float* Wk    = (const float*)d_in[3];
    const float* Wv    = (const float*)d_in[4];
    const float* Wo    = (const float*)d_in[5];
    const float* gamma = (const float*)d_in[6];
    const float* beta  = (const float*)d_in[7];
    float* out = (float*)d_out;

    const int* src = eidx;
    const int* dst = eidx + NE;

    cudaFuncSetAttribute(mma_gemm_kernel,
                         cudaFuncAttributeMaxDynamicSharedMemorySize, GEMM_SMEM);
    cudaFuncSetAttribute(gemm_ln_kernel,
                         cudaFuncAttributeMaxDynamicSharedMemorySize, FUSED_SMEM);

    // side stream + fork/join events (handles created once; no device mem)
    static cudaStream_t s2 = nullptr;
    static cudaEvent_t eA = nullptr, eB = nullptr, eE = nullptr;
    if (s2 == nullptr) {
        cudaStreamCreateWithFlags(&s2, cudaStreamNonBlocking);
        cudaEventCreateWithFlags(&eA, cudaEventDisableTiming);
        cudaEventCreateWithFlags(&eB, cudaEventDisableTiming);
        cudaEventCreateWithFlags(&eE, cudaEventDisableTiming);
    }

    // fork at graph root: CSR build depends only on edge_index
    cudaEventRecord(eA, 0);
    cudaStreamWaitEvent(s2, eA, 0);
    hist_kernel<<<(NE + 255) / 256, 256, 0, s2>>>(src);
    scan_kernel<<<1, 1024, 0, s2>>>();
    scatter_kernel<<<(NE + 255) / 256, 256, 0, s2>>>(src, dst);
    cudaEventRecord(eB, s2);
    rezero_kernel<<<(NN + 255) / 256, 256, 0, s2>>>();  // for next execution
    cudaEventRecord(eE, s2);

    // main stream: prep -> f16 QKV GEMMs (concurrent with CSR build)
    prep_all_kernel<<<(PREP_TOTAL + 255) / 256, 256>>>(x, Wq, Wk, Wv, Wo);
    dim3 gq((NN + 127) / 128, DM / 128, 3);
    mma_gemm_kernel<<<gq, 256, GEMM_SMEM>>>(NN);

    // join: aggregation needs QKV (main) and CSR (side)
    cudaStreamWaitEvent(0, eB, 0);
    node_agg_kernel<<<(NN + 7) / 8, 256>>>();

    // fused f16 output GEMM + residual + LayerNorm -> d_out
    gemm_ln_kernel<<<(NN + 63) / 64, 256, FUSED_SMEM>>>(x, gamma, beta, out, NN);

    // join rezero into the graph before capture ends
    cudaStreamWaitEvent(0, eE, 0);
}